// round 7
// baseline (speedup 1.0000x reference)
#include <cuda_runtime.h>
#include <stdint.h>

// Problem constants
#define BATCH 16384
#define HID   512
#define ALPH  64
#define SEQL  256
#define BOSID 64
#define G4    2048            // 4*HID

// ---------------- device scratch (static, allowed) ----------------
__device__ float d_h[BATCH * HID];
__device__ float d_c[BATCH * HID];
__device__ float d_gates[BATCH * G4];          // 134 MB
__device__ float d_E[(ALPH + 1) * G4];         // embed @ w_ih^T + b_ih + b_hh
__device__ float d_logits[BATCH * ALPH];
__device__ unsigned d_keys[SEQL * 2];          // keys[t] = fold-in(t) pair
__device__ unsigned g_bar = 0;
__device__ unsigned g_gen = 0;

// ---------------- grid-wide barrier (all CTAs co-resident) ----------------
__device__ __forceinline__ void gsync() {
    __threadfence();
    __syncthreads();
    if (threadIdx.x == 0) {
        unsigned nb = gridDim.x;
        unsigned gen = *(volatile unsigned*)&g_gen;
        if (atomicAdd(&g_bar, 1u) == nb - 1u) {
            atomicExch(&g_bar, 0u);
            __threadfence();
            atomicAdd(&g_gen, 1u);
        } else {
            while (*(volatile unsigned*)&g_gen == gen) __nanosleep(64);
        }
        __threadfence();
    }
    __syncthreads();
}

// ---------------- threefry2x32 (bit-exact JAX, counter mode) ----------------
__device__ __forceinline__ unsigned rotl32(unsigned v, int r) {
    return (v << r) | (v >> (32 - r));
}
__device__ __forceinline__ void tf_round(unsigned &x0, unsigned &x1, int r) {
    x0 += x1; x1 = rotl32(x1, r); x1 ^= x0;
}
__device__ __forceinline__ uint2 threefry2x32(unsigned k0, unsigned k1,
                                              unsigned x0, unsigned x1) {
    unsigned ks2 = k0 ^ k1 ^ 0x1BD11BDAu;
    x0 += k0; x1 += k1;
    tf_round(x0, x1, 13); tf_round(x0, x1, 15); tf_round(x0, x1, 26); tf_round(x0, x1, 6);
    x0 += k1; x1 += ks2 + 1u;
    tf_round(x0, x1, 17); tf_round(x0, x1, 29); tf_round(x0, x1, 16); tf_round(x0, x1, 24);
    x0 += ks2; x1 += k0 + 2u;
    tf_round(x0, x1, 13); tf_round(x0, x1, 15); tf_round(x0, x1, 26); tf_round(x0, x1, 6);
    x0 += k0; x1 += k1 + 3u;
    tf_round(x0, x1, 17); tf_round(x0, x1, 29); tf_round(x0, x1, 16); tf_round(x0, x1, 24);
    x0 += k1; x1 += ks2 + 4u;
    tf_round(x0, x1, 13); tf_round(x0, x1, 15); tf_round(x0, x1, 26); tf_round(x0, x1, 6);
    x0 += ks2; x1 += k0 + 5u;
    return make_uint2(x0, x1);
}

__device__ __forceinline__ float sigmoidf_(float x) { return 1.f / (1.f + expf(-x)); }

__device__ __forceinline__ float gumbel_from_bits(unsigned bits) {
    float u = __uint_as_float((bits >> 9) | 0x3f800000u) - 1.0f;
    u = fmaxf(1.17549435e-38f, u + 1.17549435e-38f);
    return -logf(-logf(u));
}

__device__ __forceinline__ unsigned pbits32(unsigned k0, unsigned k1, unsigned f) {
    uint2 y = threefry2x32(k0, k1, 0u, f);
    return y.x ^ y.y;
}

// packed dual-fp32 FMA (Blackwell f32x2 path; bit-identical to two scalar FFMAs)
__device__ __forceinline__ void ffma2(unsigned long long &d,
                                      unsigned long long a, unsigned long long b) {
    asm("fma.rn.f32x2 %0, %1, %2, %0;" : "+l"(d) : "l"(a), "l"(b));
}

// ---------------- main GEMM tile: gates[m0:+128][n0:+128] = h @ w_hh^T ------
// A-side smem stores every value DUPLICATED (a at [2m] and [2m+1]) so packed
// (a,a) operands come straight from LDS.128 with no per-iteration packing.
#define BM 128
#define BN 128
#define BKK 16
#define AROW 260   // padded row (floats): 16B-aligned, de-conflicts STS banks

__device__ void gemm_tile(const float* __restrict__ W, int tile) {
    static __shared__ float As2[2][BKK][AROW];  // duplicated A, 33.3 KB
    static __shared__ float Bs[2][BKK][BN];     // 16 KB
    __syncthreads();   // protect smem from previous tile / phase

    const int n0 = (tile & (G4 / BN - 1)) * BN;
    const int m0 = (tile / (G4 / BN)) * BM;
    const int tid = threadIdx.x;
    const int ty = tid >> 4;          // 0..15
    const int tx = tid & 15;          // 0..15

    unsigned long long accp[8][4];    // packed j-pairs: (acc[i][2jp], acc[i][2jp+1])
#pragma unroll
    for (int i = 0; i < 8; i++)
#pragma unroll
        for (int jp = 0; jp < 4; jp++) accp[i][jp] = 0ull;

    const int rA0 = tid >> 2, sA0 = tid & 3;
    const int rA1 = (tid + 256) >> 2, sA1 = tid & 3;

    float4 la0, la1, lb0, lb1;
    {
        const float* Ap = d_h + (size_t)(m0)*HID;
        la0 = __ldcg((const float4*)&Ap[(size_t)rA0 * HID + sA0 * 4]);
        la1 = __ldcg((const float4*)&Ap[(size_t)rA1 * HID + sA1 * 4]);
        const float* Bp = W + (size_t)(n0)*HID;
        lb0 = *(const float4*)&Bp[(size_t)rA0 * HID + sA0 * 4];
        lb1 = *(const float4*)&Bp[(size_t)rA1 * HID + sA1 * 4];
        // duplicated A stores
        As2[0][sA0 * 4 + 0][2 * rA0] = la0.x; As2[0][sA0 * 4 + 0][2 * rA0 + 1] = la0.x;
        As2[0][sA0 * 4 + 1][2 * rA0] = la0.y; As2[0][sA0 * 4 + 1][2 * rA0 + 1] = la0.y;
        As2[0][sA0 * 4 + 2][2 * rA0] = la0.z; As2[0][sA0 * 4 + 2][2 * rA0 + 1] = la0.z;
        As2[0][sA0 * 4 + 3][2 * rA0] = la0.w; As2[0][sA0 * 4 + 3][2 * rA0 + 1] = la0.w;
        As2[0][sA1 * 4 + 0][2 * rA1] = la1.x; As2[0][sA1 * 4 + 0][2 * rA1 + 1] = la1.x;
        As2[0][sA1 * 4 + 1][2 * rA1] = la1.y; As2[0][sA1 * 4 + 1][2 * rA1 + 1] = la1.y;
        As2[0][sA1 * 4 + 2][2 * rA1] = la1.z; As2[0][sA1 * 4 + 2][2 * rA1 + 1] = la1.z;
        As2[0][sA1 * 4 + 3][2 * rA1] = la1.w; As2[0][sA1 * 4 + 3][2 * rA1 + 1] = la1.w;
        Bs[0][sA0 * 4 + 0][rA0] = lb0.x; Bs[0][sA0 * 4 + 1][rA0] = lb0.y;
        Bs[0][sA0 * 4 + 2][rA0] = lb0.z; Bs[0][sA0 * 4 + 3][rA0] = lb0.w;
        Bs[0][sA1 * 4 + 0][rA1] = lb1.x; Bs[0][sA1 * 4 + 1][rA1] = lb1.y;
        Bs[0][sA1 * 4 + 2][rA1] = lb1.z; Bs[0][sA1 * 4 + 3][rA1] = lb1.w;
    }
    __syncthreads();

    int cur = 0;
    const int NT = HID / BKK;  // 32
    for (int kt = 0; kt < NT; kt++) {
        if (kt + 1 < NT) {
            const int kb = (kt + 1) * BKK;
            const float* Ap = d_h + (size_t)(m0)*HID + kb;
            la0 = __ldcg((const float4*)&Ap[(size_t)rA0 * HID + sA0 * 4]);
            la1 = __ldcg((const float4*)&Ap[(size_t)rA1 * HID + sA1 * 4]);
            const float* Bp = W + (size_t)(n0)*HID + kb;
            lb0 = *(const float4*)&Bp[(size_t)rA0 * HID + sA0 * 4];
            lb1 = *(const float4*)&Bp[(size_t)rA1 * HID + sA1 * 4];
        }
#pragma unroll
        for (int kk = 0; kk < BKK; kk++) {
            // duplicated-A packed operands: (a_i, a_i) pairs, straight LDS.128
            const ulonglong2* ap = (const ulonglong2*)&As2[cur][kk][ty * 16];
            ulonglong2 A0 = ap[0], A1 = ap[1], A2 = ap[2], A3 = ap[3];
            unsigned long long av[8] = {A0.x, A0.y, A1.x, A1.y, A2.x, A2.y, A3.x, A3.y};
            // B packed pairs straight from contiguous smem
            const ulonglong2* bp = (const ulonglong2*)&Bs[cur][kk][tx * 8];
            ulonglong2 B0 = bp[0], B1 = bp[1];
            unsigned long long bv[4] = {B0.x, B0.y, B1.x, B1.y};
#pragma unroll
            for (int i = 0; i < 8; i++)
#pragma unroll
                for (int jp = 0; jp < 4; jp++) ffma2(accp[i][jp], av[i], bv[jp]);
        }
        if (kt + 1 < NT) {
            int nxt = cur ^ 1;
            As2[nxt][sA0 * 4 + 0][2 * rA0] = la0.x; As2[nxt][sA0 * 4 + 0][2 * rA0 + 1] = la0.x;
            As2[nxt][sA0 * 4 + 1][2 * rA0] = la0.y; As2[nxt][sA0 * 4 + 1][2 * rA0 + 1] = la0.y;
            As2[nxt][sA0 * 4 + 2][2 * rA0] = la0.z; As2[nxt][sA0 * 4 + 2][2 * rA0 + 1] = la0.z;
            As2[nxt][sA0 * 4 + 3][2 * rA0] = la0.w; As2[nxt][sA0 * 4 + 3][2 * rA0 + 1] = la0.w;
            As2[nxt][sA1 * 4 + 0][2 * rA1] = la1.x; As2[nxt][sA1 * 4 + 0][2 * rA1 + 1] = la1.x;
            As2[nxt][sA1 * 4 + 1][2 * rA1] = la1.y; As2[nxt][sA1 * 4 + 1][2 * rA1 + 1] = la1.y;
            As2[nxt][sA1 * 4 + 2][2 * rA1] = la1.z; As2[nxt][sA1 * 4 + 2][2 * rA1 + 1] = la1.z;
            As2[nxt][sA1 * 4 + 3][2 * rA1] = la1.w; As2[nxt][sA1 * 4 + 3][2 * rA1 + 1] = la1.w;
            Bs[nxt][sA0 * 4 + 0][rA0] = lb0.x; Bs[nxt][sA0 * 4 + 1][rA0] = lb0.y;
            Bs[nxt][sA0 * 4 + 2][rA0] = lb0.z; Bs[nxt][sA0 * 4 + 3][rA0] = lb0.w;
            Bs[nxt][sA1 * 4 + 0][rA1] = lb1.x; Bs[nxt][sA1 * 4 + 1][rA1] = lb1.y;
            Bs[nxt][sA1 * 4 + 2][rA1] = lb1.z; Bs[nxt][sA1 * 4 + 3][rA1] = lb1.w;
            __syncthreads();
            cur = nxt;
        }
    }

    // epilogue: accp rows are exactly the 8 contiguous output floats
#pragma unroll
    for (int i = 0; i < 8; i++) {
        float* Cp = d_gates + (size_t)(m0 + ty * 8 + i) * G4 + n0 + tx * 8;
        *(float4*)&Cp[0] = *(const float4*)&accp[i][0];
        *(float4*)&Cp[4] = *(const float4*)&accp[i][2];
    }
}

// ---------------- sample for a 64-row chunk (counter-mode threefry) --------
__device__ void sample_chunk(int ch, int t, int* s_tok, float* __restrict__ out) {
    const int b0 = ch * 64;
    const int wid = threadIdx.x >> 5;
    const int lane = threadIdx.x & 31;
    const unsigned k0 = __ldcg(&d_keys[2 * t]);
    const unsigned k1 = __ldcg(&d_keys[2 * t + 1]);

    for (int rr = 0; rr < 8; rr++) {
        const int lb = wid * 8 + rr;
        const int b = b0 + lb;

        const int a0 = lane, a1 = lane + 32;
        const unsigned f0 = (unsigned)b * ALPH + a0;
        const unsigned f1 = f0 + 32u;
        unsigned bits0 = pbits32(k0, k1, f0);
        unsigned bits1 = pbits32(k0, k1, f1);

        float l0 = d_logits[(size_t)b * ALPH + a0];
        float l1 = d_logits[(size_t)b * ALPH + a1];
        float z0 = l0 + gumbel_from_bits(bits0);
        float z1 = l1 + gumbel_from_bits(bits1);

        float v; int idx;
        if (z1 > z0) { v = z1; idx = a1; } else { v = z0; idx = a0; }
#pragma unroll
        for (int off = 16; off > 0; off >>= 1) {
            float vo = __shfl_down_sync(0xffffffffu, v, off);
            int io = __shfl_down_sync(0xffffffffu, idx, off);
            if (vo > v || (vo == v && io < idx)) { v = vo; idx = io; }
        }
        idx = __shfl_sync(0xffffffffu, idx, 0);

        float m = fmaxf(l0, l1);
#pragma unroll
        for (int off = 16; off > 0; off >>= 1)
            m = fmaxf(m, __shfl_xor_sync(0xffffffffu, m, off));
        float s = expf(l0 - m) + expf(l1 - m);
#pragma unroll
        for (int off = 16; off > 0; off >>= 1)
            s += __shfl_xor_sync(0xffffffffu, s, off);

        float ltok = __shfl_sync(0xffffffffu, (idx < 32 ? l0 : l1), idx & 31);

        if (lane == 0) {
            s_tok[lb] = idx;
            out[(size_t)b * SEQL + t] = (float)idx;
            out[(size_t)BATCH * SEQL + b] += ltok - m - logf(s);
        }
    }
}

// ---------------- cell + head for a 64-row chunk ----------------
__device__ void cell_head(int ch, int use_tok, int has_gates, int czero,
                          const int* s_tok,
                          const float* __restrict__ hw, const float* __restrict__ hb) {
    const int b0 = ch * 64;
    const int tid = threadIdx.x;

    for (int e = tid; e < 64 * HID; e += 256) {
        int lr = e >> 9, k = e & (HID - 1);
        int b = b0 + lr;
        int tk = use_tok ? s_tok[lr] : BOSID;
        const float* Er = d_E + (size_t)tk * G4;
        float gi = __ldcg(&Er[k]);
        float gf = __ldcg(&Er[HID + k]);
        float gg = __ldcg(&Er[2 * HID + k]);
        float go = __ldcg(&Er[3 * HID + k]);
        if (has_gates) {
            const float* gr = d_gates + (size_t)b * G4;
            gi += __ldcg(&gr[k]);
            gf += __ldcg(&gr[HID + k]);
            gg += __ldcg(&gr[2 * HID + k]);
            go += __ldcg(&gr[3 * HID + k]);
        }
        float cc = czero ? 0.f : d_c[(size_t)b * HID + k];
        float c2 = sigmoidf_(gf) * cc + sigmoidf_(gi) * tanhf(gg);
        d_c[(size_t)b * HID + k] = c2;
        d_h[(size_t)b * HID + k] = sigmoidf_(go) * tanhf(c2);
    }
    __syncthreads();

    static __shared__ float shh[64][65];
    static __shared__ float shw[64][65];
    const int ty = tid >> 4, tx = tid & 15;
    float acc[4][4];
#pragma unroll
    for (int i = 0; i < 4; i++)
#pragma unroll
        for (int j = 0; j < 4; j++) acc[i][j] = 0.f;

    for (int kc = 0; kc < HID; kc += 64) {
#pragma unroll
        for (int q = 0; q < 4; q++) {
            int fi = tid + q * 256;
            int row = fi >> 4, c4 = fi & 15;
            float4 v = *(const float4*)&d_h[(size_t)(b0 + row) * HID + kc + c4 * 4];
            shh[row][c4 * 4 + 0] = v.x; shh[row][c4 * 4 + 1] = v.y;
            shh[row][c4 * 4 + 2] = v.z; shh[row][c4 * 4 + 3] = v.w;
            float4 w = *(const float4*)&hw[(size_t)row * HID + kc + c4 * 4];
            shw[row][c4 * 4 + 0] = w.x; shw[row][c4 * 4 + 1] = w.y;
            shw[row][c4 * 4 + 2] = w.z; shw[row][c4 * 4 + 3] = w.w;
        }
        __syncthreads();
#pragma unroll 4
        for (int kk = 0; kk < 64; kk++) {
            float av[4], bv[4];
#pragma unroll
            for (int i = 0; i < 4; i++) av[i] = shh[ty * 4 + i][kk];
#pragma unroll
            for (int j = 0; j < 4; j++) bv[j] = shw[tx * 4 + j][kk];
#pragma unroll
            for (int i = 0; i < 4; i++)
#pragma unroll
                for (int j = 0; j < 4; j++) acc[i][j] += av[i] * bv[j];
        }
        __syncthreads();
    }
#pragma unroll
    for (int i = 0; i < 4; i++)
#pragma unroll
        for (int j = 0; j < 4; j++)
            d_logits[(size_t)(b0 + ty * 4 + i) * ALPH + tx * 4 + j] = acc[i][j] + hb[tx * 4 + j];
}

// ---------------- the one persistent kernel ----------------
__global__ __launch_bounds__(256, 2)
void k_all(const float* __restrict__ embed, const float* __restrict__ w_ih,
           const float* __restrict__ w_hh, const float* __restrict__ b_ih,
           const float* __restrict__ b_hh, const float* __restrict__ head_w,
           const float* __restrict__ head_b, float* __restrict__ out) {
    __shared__ int s_tok[64];
    const int tid = threadIdx.x;
    const unsigned gtid = blockIdx.x * 256u + tid;
    const unsigned nth = gridDim.x * 256u;

    // ---- phase 0: keys (partitionable split == fold-in), logp zero, E ----
    if (blockIdx.x == 0 && tid < SEQL) {
        uint2 y = threefry2x32(0u, 42u, 0u, (unsigned)tid);
        d_keys[2 * tid]     = y.x;
        d_keys[2 * tid + 1] = y.y;
    }
    for (unsigned i = gtid; i < BATCH; i += nth)
        out[(size_t)BATCH * SEQL + i] = 0.f;
    for (unsigned idx = gtid; idx < (ALPH + 1) * G4; idx += nth) {
        int t = idx / G4, j = idx % G4;
        const float* er = embed + t * HID;
        const float* wr = w_ih + (size_t)j * HID;
        float s = b_ih[j] + b_hh[j];
#pragma unroll 8
        for (int k = 0; k < HID; k++) s += __ldg(&er[k]) * __ldg(&wr[k]);
        d_E[idx] = s;
    }
    gsync();

    // ---- BOS step ----
    for (int ch = blockIdx.x; ch < BATCH / 64; ch += gridDim.x) {
        cell_head(ch, 0, 0, 1, s_tok, head_w, head_b);
        __syncthreads();
    }
    gsync();

    // ---- main loop ----
    for (int t = 0; t < SEQL; t++) {
        if (t < SEQL - 1) {
            for (int tile = blockIdx.x; tile < (BATCH / BM) * (G4 / BN); tile += gridDim.x)
                gemm_tile(w_hh, tile);
        }
        gsync();
        for (int ch = blockIdx.x; ch < BATCH / 64; ch += gridDim.x) {
            sample_chunk(ch, t, s_tok, out);
            if (t < SEQL - 1) {
                __syncthreads();
                cell_head(ch, 1, 1, 0, s_tok, head_w, head_b);
            }
            __syncthreads();
        }
        gsync();
    }
}

// ---------------- launch ----------------
extern "C" void kernel_launch(void* const* d_in, const int* in_sizes, int n_in,
                              void* d_out, int out_size) {
    int off = (in_sizes[0] == (ALPH + 1) * HID) ? 0 : 1;
    const float* embed  = (const float*)d_in[off + 0];
    const float* w_ih   = (const float*)d_in[off + 1];
    const float* w_hh   = (const float*)d_in[off + 2];
    const float* b_ih   = (const float*)d_in[off + 3];
    const float* b_hh   = (const float*)d_in[off + 4];
    const float* head_w = (const float*)d_in[off + 5];
    const float* head_b = (const float*)d_in[off + 6];
    float* out = (float*)d_out;

    int dev = 0;
    cudaGetDevice(&dev);
    int nsm = 148;
    cudaDeviceGetAttribute(&nsm, cudaDevAttrMultiProcessorCount, dev);

    k_all<<<nsm * 2, 256>>>(embed, w_ih, w_hh, b_ih, b_hh, head_w, head_b, out);
}

// round 12
// speedup vs baseline: 1.1091x; 1.1091x over previous
#include <cuda_runtime.h>
#include <cuda_fp16.h>
#include <stdint.h>

// Problem constants
#define BATCH 16384
#define HID   512
#define ALPH  64
#define SEQL  256
#define BOSID 64
#define G4    2048            // 4*HID
#define NTILE 16              // G4/128
#define MTILE 128             // BATCH/128
#define PLANE 18432           // 128 rows x 144B (64 fp16 + 16B pad)
#define DSM_BYTES 110592      // 6 planes
#define INV2048 (1.0f/2048.0f)

// ---------------- device scratch (static, allowed) ----------------
__device__ float d_h[BATCH * HID];
__device__ float d_c[BATCH * HID];
__device__ float d_gates[BATCH * G4];     // weight-1 partial
__device__ float d_gates2[BATCH * G4];    // weight-2^-11 partial (pre-scaled)
__device__ float d_E[(ALPH + 1) * G4];
__device__ float d_logits[BATCH * ALPH];
__device__ unsigned d_keys[SEQL * 2];
// exact 3-limb fp16 decomposition (each limb renormalized): x = l0 + (l1+l2)/2048
__device__ __half d_h0[BATCH * HID], d_h1[BATCH * HID], d_h2[BATCH * HID];
__device__ __half d_W0[G4 * HID],   d_W1[G4 * HID],   d_W2[G4 * HID];
__device__ unsigned g_bar = 0;
__device__ unsigned g_gen = 0;

// ---------------- helpers ----------------
__device__ __forceinline__ uint32_t smem_to_u32(const void* p) {
    uint32_t a;
    asm("{ .reg .u64 t; cvta.to.shared.u64 t, %1; cvt.u32.u64 %0, t; }" : "=r"(a) : "l"(p));
    return a;
}

#define LDSM4(r0, r1, r2, r3, addr) \
    asm volatile("ldmatrix.sync.aligned.m8n8.x4.shared.b16 {%0,%1,%2,%3}, [%4];" \
        : "=r"(r0), "=r"(r1), "=r"(r2), "=r"(r3) : "r"(addr))

#define MMA16816(d, a, b0, b1) \
    asm volatile("mma.sync.aligned.m16n8k16.row.col.f32.f16.f16.f32 " \
        "{%0,%1,%2,%3}, {%4,%5,%6,%7}, {%8,%9}, {%0,%1,%2,%3};" \
        : "+f"((d)[0]), "+f"((d)[1]), "+f"((d)[2]), "+f"((d)[3]) \
        : "r"((a)[0]), "r"((a)[1]), "r"((a)[2]), "r"((a)[3]), "r"(b0), "r"(b1))

// multiply a packed half2 fragment reg by 2^-11 (exact scale; subnormal rounding negligible)
__device__ __forceinline__ uint32_t hdescale(uint32_t v) {
    __half2 x = *reinterpret_cast<__half2*>(&v);
    x = __hmul2(x, __half2half2(__float2half(4.8828125e-4f)));
    return *reinterpret_cast<uint32_t*>(&x);
}

// exact 3-limb split: x = l0 + l1/2048 + l2/2048 (l1 carries 2^-11 scale, l2 carries 2^-22)
__device__ __forceinline__ void split3(float x, __half& l0, __half& l1, __half& l2) {
    l0 = __float2half_rn(x);
    float r1 = x - __half2float(l0);
    l1 = __float2half_rn(r1 * 2048.f);
    float r2 = r1 - __half2float(l1) * INV2048;
    l2 = __float2half_rn(r2 * 2048.f);
}

// ---------------- grid-wide barrier (all CTAs co-resident) ----------------
__device__ __forceinline__ void gsync() {
    __threadfence();
    __syncthreads();
    if (threadIdx.x == 0) {
        unsigned nb = gridDim.x;
        unsigned gen = *(volatile unsigned*)&g_gen;
        if (atomicAdd(&g_bar, 1u) == nb - 1u) {
            atomicExch(&g_bar, 0u);
            __threadfence();
            atomicAdd(&g_gen, 1u);
        } else {
            while (*(volatile unsigned*)&g_gen == gen) __nanosleep(64);
        }
        __threadfence();
    }
    __syncthreads();
}

// ---------------- threefry2x32 (bit-exact JAX, counter mode) ----------------
__device__ __forceinline__ unsigned rotl32(unsigned v, int r) {
    return (v << r) | (v >> (32 - r));
}
__device__ __forceinline__ void tf_round(unsigned &x0, unsigned &x1, int r) {
    x0 += x1; x1 = rotl32(x1, r); x1 ^= x0;
}
__device__ __forceinline__ uint2 threefry2x32(unsigned k0, unsigned k1,
                                              unsigned x0, unsigned x1) {
    unsigned ks2 = k0 ^ k1 ^ 0x1BD11BDAu;
    x0 += k0; x1 += k1;
    tf_round(x0, x1, 13); tf_round(x0, x1, 15); tf_round(x0, x1, 26); tf_round(x0, x1, 6);
    x0 += k1; x1 += ks2 + 1u;
    tf_round(x0, x1, 17); tf_round(x0, x1, 29); tf_round(x0, x1, 16); tf_round(x0, x1, 24);
    x0 += ks2; x1 += k0 + 2u;
    tf_round(x0, x1, 13); tf_round(x0, x1, 15); tf_round(x0, x1, 26); tf_round(x0, x1, 6);
    x0 += k0; x1 += k1 + 3u;
    tf_round(x0, x1, 17); tf_round(x0, x1, 29); tf_round(x0, x1, 16); tf_round(x0, x1, 24);
    x0 += k1; x1 += ks2 + 4u;
    tf_round(x0, x1, 13); tf_round(x0, x1, 15); tf_round(x0, x1, 26); tf_round(x0, x1, 6);
    x0 += ks2; x1 += k0 + 5u;
    return make_uint2(x0, x1);
}
__device__ __forceinline__ float sigmoidf_(float x) { return 1.f / (1.f + expf(-x)); }
__device__ __forceinline__ float gumbel_from_bits(unsigned bits) {
    float u = __uint_as_float((bits >> 9) | 0x3f800000u) - 1.0f;
    u = fmaxf(1.17549435e-38f, u + 1.17549435e-38f);
    return -logf(-logf(u));
}
__device__ __forceinline__ unsigned pbits32(unsigned k0, unsigned k1, unsigned f) {
    uint2 y = threefry2x32(k0, k1, 0u, f);
    return y.x ^ y.y;
}

// ---------------- HMMA GEMM: gates = h @ w_hh^T, exact 3-limb scheme --------
// Plane slots in dsm: 0:A-l0 1:A-l1 2:A-l2 3:B-l0 4:B-l1 5:B-l2 (each PLANE bytes)

// pass1: acc1 = l0 @ g0  -> d_gates (weight 1)
__device__ void gemm_pass1(int tile, char* dsm, uint32_t dsm_u32) {
    const int n0 = (tile & (NTILE - 1)) * 128;
    const int m0 = (tile / NTILE) * 128;
    const int tid = threadIdx.x;
    const int wid = tid >> 5;
    const int lane = tid & 31;
    const int mwarp = wid >> 1;
    const int nwarp = wid & 1;

    float acc[2][8][4];
#pragma unroll
    for (int mi = 0; mi < 2; mi++)
#pragma unroll
        for (int ni = 0; ni < 8; ni++)
#pragma unroll
            for (int e = 0; e < 4; e++) acc[mi][ni][e] = 0.f;

    const int a_r = (lane & 15);
    const int a_c2 = ((lane >> 4) << 3) * 2;
    const int b_r = ((lane >> 4) << 3) + (lane & 7);
    const int b_c2 = (((lane >> 3) & 1) << 3) * 2;
    const uint32_t pA0 = dsm_u32;
    const uint32_t pB0 = dsm_u32 + 3 * PLANE;

    for (int c = 0; c < 8; c++) {
        const int kb = c * 64;
        __syncthreads();
        for (int q = tid; q < 2048; q += 256) {
            int p = q >> 10;
            int r = (q & 1023) >> 3, sg = q & 7;
            const __half* s = p ? d_W0 : d_h0;
            size_t rb = p ? (size_t)n0 : (size_t)m0;
            char* pl = dsm + (p ? 3 * PLANE : 0);
            uint4 v = __ldcg((const uint4*)&s[(rb + r) * HID + kb + sg * 8]);
            *(uint4*)(pl + r * 144 + sg * 16) = v;
        }
        __syncthreads();

#pragma unroll
        for (int kk = 0; kk < 4; kk++) {
            const int kB = kk * 32;
            uint32_t a0[2][4], bfr[4][4];
#pragma unroll
            for (int mi = 0; mi < 2; mi++) {
                uint32_t off = (uint32_t)(mwarp * 32 + mi * 16 + a_r) * 144 + kB + a_c2;
                LDSM4(a0[mi][0], a0[mi][1], a0[mi][2], a0[mi][3], pA0 + off);
            }
#pragma unroll
            for (int p4 = 0; p4 < 4; p4++) {
                uint32_t off = (uint32_t)(nwarp * 64 + p4 * 16 + b_r) * 144 + kB + b_c2;
                LDSM4(bfr[p4][0], bfr[p4][1], bfr[p4][2], bfr[p4][3], pB0 + off);
            }
#pragma unroll
            for (int mi = 0; mi < 2; mi++)
#pragma unroll
                for (int p4 = 0; p4 < 4; p4++) {
                    MMA16816(acc[mi][2 * p4], a0[mi], bfr[p4][0], bfr[p4][1]);
                    MMA16816(acc[mi][2 * p4 + 1], a0[mi], bfr[p4][2], bfr[p4][3]);
                }
        }
    }

    const int g = lane >> 2, t4 = lane & 3;
#pragma unroll
    for (int mi = 0; mi < 2; mi++) {
        const int row = m0 + mwarp * 32 + mi * 16 + g;
#pragma unroll
        for (int ni = 0; ni < 8; ni++) {
            const int col = n0 + nwarp * 64 + ni * 8 + 2 * t4;
            float* Cp = d_gates + (size_t)row * G4 + col;
            Cp[0] = acc[mi][ni][0];
            Cp[1] = acc[mi][ni][1];
            float* Cp2 = Cp + (size_t)8 * G4;
            Cp2[0] = acc[mi][ni][2];
            Cp2[1] = acc[mi][ni][3];
        }
    }
}

// pass2: acc2 = l0@g1 + l1@g0 + l0@g2 + l2@g0 + (l1*2^-11)@g1 -> d_gates2 * 2^-11
__device__ void gemm_pass2(int tile, char* dsm, uint32_t dsm_u32) {
    const int n0 = (tile & (NTILE - 1)) * 128;
    const int m0 = (tile / NTILE) * 128;
    const int tid = threadIdx.x;
    const int wid = tid >> 5;
    const int lane = tid & 31;
    const int mwarp = wid >> 1;
    const int nwarp = wid & 1;

    float acc[2][8][4];
#pragma unroll
    for (int mi = 0; mi < 2; mi++)
#pragma unroll
        for (int ni = 0; ni < 8; ni++)
#pragma unroll
            for (int e = 0; e < 4; e++) acc[mi][ni][e] = 0.f;

    const int a_r = (lane & 15);
    const int a_c2 = ((lane >> 4) << 3) * 2;
    const int b_r = ((lane >> 4) << 3) + (lane & 7);
    const int b_c2 = (((lane >> 3) & 1) << 3) * 2;

    for (int c = 0; c < 8; c++) {
        const int kb = c * 64;
        __syncthreads();
        {
            const __half* srcs[6] = {d_h0, d_h1, d_h2, d_W0, d_W1, d_W2};
#pragma unroll
            for (int p = 0; p < 6; p++) {
                const __half* s = srcs[p];
                const size_t rb = (p < 3) ? (size_t)m0 : (size_t)n0;
                char* pl = dsm + p * PLANE;
                for (int q = tid; q < 1024; q += 256) {
                    int r = q >> 3, sg = q & 7;
                    uint4 v = __ldcg((const uint4*)&s[(rb + r) * HID + kb + sg * 8]);
                    *(uint4*)(pl + r * 144 + sg * 16) = v;
                }
            }
        }
        __syncthreads();

#pragma unroll
        for (int kk = 0; kk < 4; kk++) {
            const int kB = kk * 32;
            uint32_t a0[2][4], a1[2][4], a1d[2][4], a2[2][4];
#pragma unroll
            for (int mi = 0; mi < 2; mi++) {
                uint32_t off = (uint32_t)(mwarp * 32 + mi * 16 + a_r) * 144 + kB + a_c2;
                LDSM4(a0[mi][0], a0[mi][1], a0[mi][2], a0[mi][3], dsm_u32 + off);
                LDSM4(a1[mi][0], a1[mi][1], a1[mi][2], a1[mi][3], dsm_u32 + PLANE + off);
                LDSM4(a2[mi][0], a2[mi][1], a2[mi][2], a2[mi][3], dsm_u32 + 2 * PLANE + off);
#pragma unroll
                for (int j = 0; j < 4; j++) a1d[mi][j] = hdescale(a1[mi][j]);
            }
#pragma unroll
            for (int nh = 0; nh < 2; nh++) {
                uint32_t b0[2][4], b1[2][4], b2[2][4];
#pragma unroll
                for (int q = 0; q < 2; q++) {
                    int p4 = nh * 2 + q;
                    uint32_t off = (uint32_t)(nwarp * 64 + p4 * 16 + b_r) * 144 + kB + b_c2;
                    LDSM4(b0[q][0], b0[q][1], b0[q][2], b0[q][3], dsm_u32 + 3 * PLANE + off);
                    LDSM4(b1[q][0], b1[q][1], b1[q][2], b1[q][3], dsm_u32 + 4 * PLANE + off);
                    LDSM4(b2[q][0], b2[q][1], b2[q][2], b2[q][3], dsm_u32 + 5 * PLANE + off);
                }
#pragma unroll
                for (int mi = 0; mi < 2; mi++)
#pragma unroll
                    for (int q = 0; q < 2; q++) {
                        const int ni0 = 2 * (nh * 2 + q), ni1 = ni0 + 1;
                        MMA16816(acc[mi][ni0], a0[mi], b1[q][0], b1[q][1]);   // l0*g1
                        MMA16816(acc[mi][ni1], a0[mi], b1[q][2], b1[q][3]);
                        MMA16816(acc[mi][ni0], a1[mi], b0[q][0], b0[q][1]);   // l1*g0
                        MMA16816(acc[mi][ni1], a1[mi], b0[q][2], b0[q][3]);
                        MMA16816(acc[mi][ni0], a0[mi], b2[q][0], b2[q][1]);   // l0*g2
                        MMA16816(acc[mi][ni1], a0[mi], b2[q][2], b2[q][3]);
                        MMA16816(acc[mi][ni0], a2[mi], b0[q][0], b0[q][1]);   // l2*g0
                        MMA16816(acc[mi][ni1], a2[mi], b0[q][2], b0[q][3]);
                        MMA16816(acc[mi][ni0], a1d[mi], b1[q][0], b1[q][1]);  // (l1*2^-11)*g1
                        MMA16816(acc[mi][ni1], a1d[mi], b1[q][2], b1[q][3]);
                    }
            }
        }
    }

    const int g = lane >> 2, t4 = lane & 3;
#pragma unroll
    for (int mi = 0; mi < 2; mi++) {
        const int row = m0 + mwarp * 32 + mi * 16 + g;
#pragma unroll
        for (int ni = 0; ni < 8; ni++) {
            const int col = n0 + nwarp * 64 + ni * 8 + 2 * t4;
            float* Cp = d_gates2 + (size_t)row * G4 + col;
            Cp[0] = acc[mi][ni][0] * INV2048;
            Cp[1] = acc[mi][ni][1] * INV2048;
            float* Cp2 = Cp + (size_t)8 * G4;
            Cp2[0] = acc[mi][ni][2] * INV2048;
            Cp2[1] = acc[mi][ni][3] * INV2048;
        }
    }
}

// ---------------- sample for a 64-row chunk (counter-mode threefry) --------
__device__ void sample_chunk(int ch, int t, int* s_tok, float* __restrict__ out) {
    const int b0 = ch * 64;
    const int wid = threadIdx.x >> 5;
    const int lane = threadIdx.x & 31;
    const unsigned k0 = __ldcg(&d_keys[2 * t]);
    const unsigned k1 = __ldcg(&d_keys[2 * t + 1]);

    for (int rr = 0; rr < 8; rr++) {
        const int lb = wid * 8 + rr;
        const int b = b0 + lb;

        const int a0 = lane, a1 = lane + 32;
        const unsigned f0 = (unsigned)b * ALPH + a0;
        const unsigned f1 = f0 + 32u;
        unsigned bits0 = pbits32(k0, k1, f0);
        unsigned bits1 = pbits32(k0, k1, f1);

        float l0 = d_logits[(size_t)b * ALPH + a0];
        float l1 = d_logits[(size_t)b * ALPH + a1];
        float z0 = l0 + gumbel_from_bits(bits0);
        float z1 = l1 + gumbel_from_bits(bits1);

        float v; int idx;
        if (z1 > z0) { v = z1; idx = a1; } else { v = z0; idx = a0; }
#pragma unroll
        for (int off = 16; off > 0; off >>= 1) {
            float vo = __shfl_down_sync(0xffffffffu, v, off);
            int io = __shfl_down_sync(0xffffffffu, idx, off);
            if (vo > v || (vo == v && io < idx)) { v = vo; idx = io; }
        }
        idx = __shfl_sync(0xffffffffu, idx, 0);

        float m = fmaxf(l0, l1);
#pragma unroll
        for (int off = 16; off > 0; off >>= 1)
            m = fmaxf(m, __shfl_xor_sync(0xffffffffu, m, off));
        float s = expf(l0 - m) + expf(l1 - m);
#pragma unroll
        for (int off = 16; off > 0; off >>= 1)
            s += __shfl_xor_sync(0xffffffffu, s, off);

        float ltok = __shfl_sync(0xffffffffu, (idx < 32 ? l0 : l1), idx & 31);

        if (lane == 0) {
            s_tok[lb] = idx;
            out[(size_t)b * SEQL + t] = (float)idx;
            out[(size_t)BATCH * SEQL + b] += ltok - m - logf(s);
        }
    }
}

// ---------------- cell + head for a 64-row chunk ----------------
__device__ void cell_head(int ch, int use_tok, int has_gates, int czero,
                          const int* s_tok, char* pchar,
                          const float* __restrict__ hw, const float* __restrict__ hb) {
    const int b0 = ch * 64;
    const int tid = threadIdx.x;

    for (int e = tid; e < 64 * HID; e += 256) {
        int lr = e >> 9, k = e & (HID - 1);
        int b = b0 + lr;
        int tk = use_tok ? s_tok[lr] : BOSID;
        const float* Er = d_E + (size_t)tk * G4;
        float gi = __ldcg(&Er[k]);
        float gf = __ldcg(&Er[HID + k]);
        float gg = __ldcg(&Er[2 * HID + k]);
        float go = __ldcg(&Er[3 * HID + k]);
        if (has_gates) {
            const float* g1 = d_gates + (size_t)b * G4;
            const float* g2 = d_gates2 + (size_t)b * G4;
            gi += __ldcg(&g1[k]) + __ldcg(&g2[k]);
            gf += __ldcg(&g1[HID + k]) + __ldcg(&g2[HID + k]);
            gg += __ldcg(&g1[2 * HID + k]) + __ldcg(&g2[2 * HID + k]);
            go += __ldcg(&g1[3 * HID + k]) + __ldcg(&g2[3 * HID + k]);
        }
        size_t i = (size_t)b * HID + k;
        float cc = czero ? 0.f : d_c[i];
        float c2 = sigmoidf_(gf) * cc + sigmoidf_(gi) * tanhf(gg);
        d_c[i] = c2;
        float h2 = sigmoidf_(go) * tanhf(c2);
        d_h[i] = h2;
        __half q0, q1, q2;
        split3(h2, q0, q1, q2);
        d_h0[i] = q0; d_h1[i] = q1; d_h2[i] = q2;
    }
    __syncthreads();

    // head: logits[64x64] = h @ head_w^T + head_b  (smem overlaid on gemm planes)
    float (*shh)[65] = (float (*)[65])pchar;
    float (*shw)[65] = (float (*)[65])(pchar + 64 * 65 * 4);
    const int ty = tid >> 4, tx = tid & 15;
    float acc[4][4];
#pragma unroll
    for (int i = 0; i < 4; i++)
#pragma unroll
        for (int j = 0; j < 4; j++) acc[i][j] = 0.f;

    for (int kc = 0; kc < HID; kc += 64) {
#pragma unroll
        for (int q = 0; q < 4; q++) {
            int fi = tid + q * 256;
            int row = fi >> 4, c4 = fi & 15;
            float4 v = *(const float4*)&d_h[(size_t)(b0 + row) * HID + kc + c4 * 4];
            shh[row][c4 * 4 + 0] = v.x; shh[row][c4 * 4 + 1] = v.y;
            shh[row][c4 * 4 + 2] = v.z; shh[row][c4 * 4 + 3] = v.w;
            float4 w = *(const float4*)&hw[(size_t)row * HID + kc + c4 * 4];
            shw[row][c4 * 4 + 0] = w.x; shw[row][c4 * 4 + 1] = w.y;
            shw[row][c4 * 4 + 2] = w.z; shw[row][c4 * 4 + 3] = w.w;
        }
        __syncthreads();
#pragma unroll 4
        for (int kk = 0; kk < 64; kk++) {
            float av[4], bv[4];
#pragma unroll
            for (int i = 0; i < 4; i++) av[i] = shh[ty * 4 + i][kk];
#pragma unroll
            for (int j = 0; j < 4; j++) bv[j] = shw[tx * 4 + j][kk];
#pragma unroll
            for (int i = 0; i < 4; i++)
#pragma unroll
                for (int j = 0; j < 4; j++) acc[i][j] += av[i] * bv[j];
        }
        __syncthreads();
    }
#pragma unroll
    for (int i = 0; i < 4; i++)
#pragma unroll
        for (int j = 0; j < 4; j++)
            d_logits[(size_t)(b0 + ty * 4 + i) * ALPH + tx * 4 + j] = acc[i][j] + hb[tx * 4 + j];
}

// ---------------- the one persistent kernel ----------------
__global__ __launch_bounds__(256, 2)
void k_all(const float* __restrict__ embed, const float* __restrict__ w_ih,
           const float* __restrict__ w_hh, const float* __restrict__ b_ih,
           const float* __restrict__ b_hh, const float* __restrict__ head_w,
           const float* __restrict__ head_b, float* __restrict__ out) {
    extern __shared__ __align__(16) char dsm[];
    __shared__ int s_tok[64];
    const int tid = threadIdx.x;
    const unsigned gtid = blockIdx.x * 256u + tid;
    const unsigned nth = gridDim.x * 256u;
    const uint32_t dsm_u32 = smem_to_u32(dsm);

    // ---- phase 0: keys, logp zero, E precompute, W 3-limb split ----
    if (blockIdx.x == 0 && tid < SEQL) {
        uint2 y = threefry2x32(0u, 42u, 0u, (unsigned)tid);
        d_keys[2 * tid]     = y.x;
        d_keys[2 * tid + 1] = y.y;
    }
    for (unsigned i = gtid; i < BATCH; i += nth)
        out[(size_t)BATCH * SEQL + i] = 0.f;
    for (unsigned idx = gtid; idx < (ALPH + 1) * G4; idx += nth) {
        int t = idx / G4, j = idx % G4;
        const float* er = embed + t * HID;
        const float* wr = w_ih + (size_t)j * HID;
        float s = b_ih[j] + b_hh[j];
#pragma unroll 8
        for (int k = 0; k < HID; k++) s += __ldg(&er[k]) * __ldg(&wr[k]);
        d_E[idx] = s;
    }
    for (unsigned idx = gtid; idx < (unsigned)G4 * HID; idx += nth) {
        __half q0, q1, q2;
        split3(w_hh[idx], q0, q1, q2);
        d_W0[idx] = q0; d_W1[idx] = q1; d_W2[idx] = q2;
    }
    gsync();

    // ---- BOS step ----
    for (int ch = blockIdx.x; ch < BATCH / 64; ch += gridDim.x) {
        cell_head(ch, 0, 0, 1, s_tok, dsm, head_w, head_b);
        __syncthreads();
    }
    gsync();

    // ---- main loop ----
    for (int t = 0; t < SEQL; t++) {
        if (t < SEQL - 1) {
            for (int tile = blockIdx.x; tile < MTILE * NTILE; tile += gridDim.x) {
                gemm_pass1(tile, dsm, dsm_u32);
                gemm_pass2(tile, dsm, dsm_u32);
            }
        }
        gsync();
        for (int ch = blockIdx.x; ch < BATCH / 64; ch += gridDim.x) {
            sample_chunk(ch, t, s_tok, out);
            if (t < SEQL - 1) {
                __syncthreads();
                cell_head(ch, 1, 1, 0, s_tok, dsm, head_w, head_b);
            }
            __syncthreads();
        }
        gsync();
    }
}

// ---------------- launch ----------------
extern "C" void kernel_launch(void* const* d_in, const int* in_sizes, int n_in,
                              void* d_out, int out_size) {
    int off = (in_sizes[0] == (ALPH + 1) * HID) ? 0 : 1;
    const float* embed  = (const float*)d_in[off + 0];
    const float* w_ih   = (const float*)d_in[off + 1];
    const float* w_hh   = (const float*)d_in[off + 2];
    const float* b_ih   = (const float*)d_in[off + 3];
    const float* b_hh   = (const float*)d_in[off + 4];
    const float* head_w = (const float*)d_in[off + 5];
    const float* head_b = (const float*)d_in[off + 6];
    float* out = (float*)d_out;

    int dev = 0;
    cudaGetDevice(&dev);
    int nsm = 148;
    cudaDeviceGetAttribute(&nsm, cudaDevAttrMultiProcessorCount, dev);

    cudaFuncSetAttribute(k_all, cudaFuncAttributeMaxDynamicSharedMemorySize, DSM_BYTES);

    // grid must exactly match co-resident capacity for the gsync barrier
    int occ = 1;
    if (cudaOccupancyMaxActiveBlocksPerMultiprocessor(&occ, k_all, 256, DSM_BYTES)
        != cudaSuccess || occ < 1)
        occ = 1;
    if (occ > 2) occ = 2;

    k_all<<<nsm * occ, 256, DSM_BYTES>>>(embed, w_ih, w_hh, b_ih, b_hh,
                                         head_w, head_b, out);
}

// round 14
// speedup vs baseline: 1.5804x; 1.4250x over previous
#include <cuda_runtime.h>
#include <cuda_fp16.h>
#include <stdint.h>

// Problem constants
#define BATCH 16384
#define HID   512
#define ALPH  64
#define SEQL  256
#define BOSID 64
#define G4    2048            // 4*HID
#define NTILE 16              // G4/128
#define MTILE 128             // BATCH/128
#define PLANE 18432           // 128 rows x 144B (64 fp16 + 16B pad)
#define BUFSZ (6 * PLANE)     // 110592: one 6-plane chunk buffer
#define DSM_BYTES (2 * BUFSZ) // 221184: double-buffered
#define INV2048 (1.0f/2048.0f)
#define NTHREADS 512

// ---------------- device scratch (static, allowed) ----------------
__device__ float d_h[BATCH * HID];
__device__ float d_c[BATCH * HID];
__device__ float d_gates[BATCH * G4];     // full gate partial (acc1 + acc2/2048)
__device__ float d_E[(ALPH + 1) * G4];
__device__ float d_logits[BATCH * ALPH];
__device__ unsigned d_keys[SEQL * 2];
// exact 3-limb fp16 decomposition (each limb renormalized): x = l0 + (l1+l2)/2048
__device__ __half d_h0[BATCH * HID], d_h1[BATCH * HID], d_h2[BATCH * HID];
__device__ __half d_W0[G4 * HID],   d_W1[G4 * HID],   d_W2[G4 * HID];
__device__ unsigned g_bar = 0;
__device__ unsigned g_gen = 0;

// ---------------- helpers ----------------
__device__ __forceinline__ uint32_t smem_to_u32(const void* p) {
    uint32_t a;
    asm("{ .reg .u64 t; cvta.to.shared.u64 t, %1; cvt.u32.u64 %0, t; }" : "=r"(a) : "l"(p));
    return a;
}

#define LDSM4(r0, r1, r2, r3, addr) \
    asm volatile("ldmatrix.sync.aligned.m8n8.x4.shared.b16 {%0,%1,%2,%3}, [%4];" \
        : "=r"(r0), "=r"(r1), "=r"(r2), "=r"(r3) : "r"(addr))

#define MMA16816(d, a, b0, b1) \
    asm volatile("mma.sync.aligned.m16n8k16.row.col.f32.f16.f16.f32 " \
        "{%0,%1,%2,%3}, {%4,%5,%6,%7}, {%8,%9}, {%0,%1,%2,%3};" \
        : "+f"((d)[0]), "+f"((d)[1]), "+f"((d)[2]), "+f"((d)[3]) \
        : "r"((a)[0]), "r"((a)[1]), "r"((a)[2]), "r"((a)[3]), "r"(b0), "r"(b1))

#define CP_ASYNC16(saddr, gaddr) \
    asm volatile("cp.async.cg.shared.global [%0], [%1], 16;" :: "r"(saddr), "l"(gaddr) : "memory")
#define CP_COMMIT() asm volatile("cp.async.commit_group;" ::: "memory")
#define CP_WAIT1()  asm volatile("cp.async.wait_group 1;" ::: "memory")
#define CP_WAIT0()  asm volatile("cp.async.wait_group 0;" ::: "memory")

// multiply a packed half2 fragment reg by 2^-11 (exact scale)
__device__ __forceinline__ uint32_t hdescale(uint32_t v) {
    __half2 x = *reinterpret_cast<__half2*>(&v);
    x = __hmul2(x, __half2half2(__float2half(4.8828125e-4f)));
    return *reinterpret_cast<uint32_t*>(&x);
}

// exact 3-limb split: x = l0 + l1/2048 + l2/2048
__device__ __forceinline__ void split3(float x, __half& l0, __half& l1, __half& l2) {
    l0 = __float2half_rn(x);
    float r1 = x - __half2float(l0);
    l1 = __float2half_rn(r1 * 2048.f);
    float r2 = r1 - __half2float(l1) * INV2048;
    l2 = __float2half_rn(r2 * 2048.f);
}

// ---------------- grid-wide barrier (all CTAs co-resident) ----------------
__device__ __forceinline__ void gsync() {
    __threadfence();
    __syncthreads();
    if (threadIdx.x == 0) {
        unsigned nb = gridDim.x;
        unsigned gen = *(volatile unsigned*)&g_gen;
        if (atomicAdd(&g_bar, 1u) == nb - 1u) {
            atomicExch(&g_bar, 0u);
            __threadfence();
            atomicAdd(&g_gen, 1u);
        } else {
            while (*(volatile unsigned*)&g_gen == gen) __nanosleep(64);
        }
        __threadfence();
    }
    __syncthreads();
}

// ---------------- threefry2x32 (bit-exact JAX, counter mode) ----------------
__device__ __forceinline__ unsigned rotl32(unsigned v, int r) {
    return (v << r) | (v >> (32 - r));
}
__device__ __forceinline__ void tf_round(unsigned &x0, unsigned &x1, int r) {
    x0 += x1; x1 = rotl32(x1, r); x1 ^= x0;
}
__device__ __forceinline__ uint2 threefry2x32(unsigned k0, unsigned k1,
                                              unsigned x0, unsigned x1) {
    unsigned ks2 = k0 ^ k1 ^ 0x1BD11BDAu;
    x0 += k0; x1 += k1;
    tf_round(x0, x1, 13); tf_round(x0, x1, 15); tf_round(x0, x1, 26); tf_round(x0, x1, 6);
    x0 += k1; x1 += ks2 + 1u;
    tf_round(x0, x1, 17); tf_round(x0, x1, 29); tf_round(x0, x1, 16); tf_round(x0, x1, 24);
    x0 += ks2; x1 += k0 + 2u;
    tf_round(x0, x1, 13); tf_round(x0, x1, 15); tf_round(x0, x1, 26); tf_round(x0, x1, 6);
    x0 += k0; x1 += k1 + 3u;
    tf_round(x0, x1, 17); tf_round(x0, x1, 29); tf_round(x0, x1, 16); tf_round(x0, x1, 24);
    x0 += k1; x1 += ks2 + 4u;
    tf_round(x0, x1, 13); tf_round(x0, x1, 15); tf_round(x0, x1, 26); tf_round(x0, x1, 6);
    x0 += ks2; x1 += k0 + 5u;
    return make_uint2(x0, x1);
}
__device__ __forceinline__ float sigmoidf_(float x) { return 1.f / (1.f + expf(-x)); }
__device__ __forceinline__ float gumbel_from_bits(unsigned bits) {
    float u = __uint_as_float((bits >> 9) | 0x3f800000u) - 1.0f;
    u = fmaxf(1.17549435e-38f, u + 1.17549435e-38f);
    return -logf(-logf(u));
}
__device__ __forceinline__ unsigned pbits32(unsigned k0, unsigned k1, unsigned f) {
    uint2 y = threefry2x32(k0, k1, 0u, f);
    return y.x ^ y.y;
}

// ---------------- chunk prefetch via cp.async (6 planes, 64-K slice) --------
__device__ __forceinline__ void prefetch_chunk(int kb, int m0, int n0, uint32_t sbase) {
    const int tid = threadIdx.x;
#pragma unroll
    for (int p = 0; p < 6; p++) {
        const __half* s = (p == 0) ? d_h0 : (p == 1) ? d_h1 : (p == 2) ? d_h2
                        : (p == 3) ? d_W0 : (p == 4) ? d_W1 : d_W2;
        const size_t rb = (p < 3) ? (size_t)m0 : (size_t)n0;
#pragma unroll
        for (int qq = 0; qq < 2; qq++) {
            int q = tid + qq * NTHREADS;     // 0..1023
            int r = q >> 3, sg = q & 7;
            const void* g = (const void*)&s[(rb + r) * HID + kb + sg * 8];
            uint32_t sa = sbase + p * PLANE + (uint32_t)(r * 144 + sg * 16);
            CP_ASYNC16(sa, g);
        }
    }
}

// ---------------- merged HMMA GEMM tile (bit-identical to R12 numerics) -----
// 16 warps as 4x4; each warp 32 rows x 32 cols. Double-buffered chunks.
// acc1 <- l0@g0 (chunk,kk order); acc2 <- [l0g1, l1g0, l0g2, l2g0, l1d g1] per kk.
__device__ void gemm_tile_merged(int tile, uint32_t dsm_u32) {
    const int n0 = (tile & (NTILE - 1)) * 128;
    const int m0 = (tile / NTILE) * 128;
    const int tid = threadIdx.x;
    const int wid = tid >> 5;
    const int lane = tid & 31;
    const int mwarp = wid >> 2;      // 0..3
    const int nwarp = wid & 3;       // 0..3

    float acc1[2][4][4], acc2[2][4][4];
#pragma unroll
    for (int mi = 0; mi < 2; mi++)
#pragma unroll
        for (int ni = 0; ni < 4; ni++)
#pragma unroll
            for (int e = 0; e < 4; e++) { acc1[mi][ni][e] = 0.f; acc2[mi][ni][e] = 0.f; }

    const int a_r = (lane & 15);
    const int a_c2 = ((lane >> 4) << 3) * 2;
    const int b_r = ((lane >> 4) << 3) + (lane & 7);
    const int b_c2 = (((lane >> 3) & 1) << 3) * 2;

    prefetch_chunk(0, m0, n0, dsm_u32);
    CP_COMMIT();

    for (int c = 0; c < 8; c++) {
        const uint32_t bufr = dsm_u32 + (uint32_t)(c & 1) * BUFSZ;
        if (c + 1 < 8) {
            prefetch_chunk((c + 1) * 64, m0, n0, dsm_u32 + (uint32_t)((c + 1) & 1) * BUFSZ);
            CP_COMMIT();
            CP_WAIT1();
        } else {
            CP_WAIT0();
        }
        __syncthreads();

#pragma unroll
        for (int kk = 0; kk < 4; kk++) {
            const int kB = kk * 32;
            uint32_t a0[2][4], a1[2][4], a1d[2][4], a2[2][4];
#pragma unroll
            for (int mi = 0; mi < 2; mi++) {
                uint32_t off = (uint32_t)(mwarp * 32 + mi * 16 + a_r) * 144 + kB + a_c2;
                LDSM4(a0[mi][0], a0[mi][1], a0[mi][2], a0[mi][3], bufr + off);
                LDSM4(a1[mi][0], a1[mi][1], a1[mi][2], a1[mi][3], bufr + PLANE + off);
                LDSM4(a2[mi][0], a2[mi][1], a2[mi][2], a2[mi][3], bufr + 2 * PLANE + off);
#pragma unroll
                for (int j = 0; j < 4; j++) a1d[mi][j] = hdescale(a1[mi][j]);
            }
#pragma unroll
            for (int grp = 0; grp < 2; grp++) {
                uint32_t off = (uint32_t)(nwarp * 32 + grp * 16 + b_r) * 144 + kB + b_c2;
                uint32_t b0[4], b1[4], b2[4];
                LDSM4(b0[0], b0[1], b0[2], b0[3], bufr + 3 * PLANE + off);
                LDSM4(b1[0], b1[1], b1[2], b1[3], bufr + 4 * PLANE + off);
                LDSM4(b2[0], b2[1], b2[2], b2[3], bufr + 5 * PLANE + off);
                const int ni0 = 2 * grp, ni1 = ni0 + 1;
#pragma unroll
                for (int mi = 0; mi < 2; mi++) {
                    // acc1: l0*g0 (only product; order = chunk,kk)
                    MMA16816(acc1[mi][ni0], a0[mi], b0[0], b0[1]);
                    MMA16816(acc1[mi][ni1], a0[mi], b0[2], b0[3]);
                    // acc2: canonical 5-product order per kk
                    MMA16816(acc2[mi][ni0], a0[mi], b1[0], b1[1]);   // l0*g1
                    MMA16816(acc2[mi][ni1], a0[mi], b1[2], b1[3]);
                    MMA16816(acc2[mi][ni0], a1[mi], b0[0], b0[1]);   // l1*g0
                    MMA16816(acc2[mi][ni1], a1[mi], b0[2], b0[3]);
                    MMA16816(acc2[mi][ni0], a0[mi], b2[0], b2[1]);   // l0*g2
                    MMA16816(acc2[mi][ni1], a0[mi], b2[2], b2[3]);
                    MMA16816(acc2[mi][ni0], a2[mi], b0[0], b0[1]);   // l2*g0
                    MMA16816(acc2[mi][ni1], a2[mi], b0[2], b0[3]);
                    MMA16816(acc2[mi][ni0], a1d[mi], b1[0], b1[1]);  // (l1*2^-11)*g1
                    MMA16816(acc2[mi][ni1], a1d[mi], b1[2], b1[3]);
                }
            }
        }
        __syncthreads();
    }

    // epilogue: gate = acc1 + acc2 * 2^-11 (multiply exact; same rounding as R12)
    const int g = lane >> 2, t4 = lane & 3;
#pragma unroll
    for (int mi = 0; mi < 2; mi++) {
        const int row = m0 + mwarp * 32 + mi * 16 + g;
#pragma unroll
        for (int ni = 0; ni < 4; ni++) {
            const int col = n0 + nwarp * 32 + ni * 8 + 2 * t4;
            float* Cp = d_gates + (size_t)row * G4 + col;
            Cp[0] = acc1[mi][ni][0] + acc2[mi][ni][0] * INV2048;
            Cp[1] = acc1[mi][ni][1] + acc2[mi][ni][1] * INV2048;
            float* Cp2 = Cp + (size_t)8 * G4;
            Cp2[0] = acc1[mi][ni][2] + acc2[mi][ni][2] * INV2048;
            Cp2[1] = acc1[mi][ni][3] + acc2[mi][ni][3] * INV2048;
        }
    }
}

// ---------------- sample for a 64-row chunk (256-thread half) ---------------
__device__ void sample_chunk(int ch, int t, int* stok, float* __restrict__ out, int htid) {
    const int b0 = ch * 64;
    const int hwid = htid >> 5;
    const int lane = htid & 31;
    const unsigned k0 = __ldcg(&d_keys[2 * t]);
    const unsigned k1 = __ldcg(&d_keys[2 * t + 1]);

    for (int rr = 0; rr < 8; rr++) {
        const int lb = hwid * 8 + rr;
        const int b = b0 + lb;

        const int a0 = lane, a1 = lane + 32;
        const unsigned f0 = (unsigned)b * ALPH + a0;
        const unsigned f1 = f0 + 32u;
        unsigned bits0 = pbits32(k0, k1, f0);
        unsigned bits1 = pbits32(k0, k1, f1);

        float l0 = d_logits[(size_t)b * ALPH + a0];
        float l1 = d_logits[(size_t)b * ALPH + a1];
        float z0 = l0 + gumbel_from_bits(bits0);
        float z1 = l1 + gumbel_from_bits(bits1);

        float v; int idx;
        if (z1 > z0) { v = z1; idx = a1; } else { v = z0; idx = a0; }
#pragma unroll
        for (int off = 16; off > 0; off >>= 1) {
            float vo = __shfl_down_sync(0xffffffffu, v, off);
            int io = __shfl_down_sync(0xffffffffu, idx, off);
            if (vo > v || (vo == v && io < idx)) { v = vo; idx = io; }
        }
        idx = __shfl_sync(0xffffffffu, idx, 0);

        float m = fmaxf(l0, l1);
#pragma unroll
        for (int off = 16; off > 0; off >>= 1)
            m = fmaxf(m, __shfl_xor_sync(0xffffffffu, m, off));
        float s = expf(l0 - m) + expf(l1 - m);
#pragma unroll
        for (int off = 16; off > 0; off >>= 1)
            s += __shfl_xor_sync(0xffffffffu, s, off);

        float ltok = __shfl_sync(0xffffffffu, (idx < 32 ? l0 : l1), idx & 31);

        if (lane == 0) {
            stok[lb] = idx;
            out[(size_t)b * SEQL + t] = (float)idx;
            out[(size_t)BATCH * SEQL + b] += ltok - m - logf(s);
        }
    }
}

// ---------------- cell + head for a 64-row chunk (256-thread half) ----------
__device__ void cell_head(int ch, int use_tok, int has_gates, int czero,
                          const int* stok, char* pchar,
                          const float* __restrict__ hw, const float* __restrict__ hb,
                          int htid) {
    const int b0 = ch * 64;

    for (int e = htid; e < 64 * HID; e += 256) {
        int lr = e >> 9, k = e & (HID - 1);
        int b = b0 + lr;
        int tk = use_tok ? stok[lr] : BOSID;
        const float* Er = d_E + (size_t)tk * G4;
        float gi = __ldcg(&Er[k]);
        float gf = __ldcg(&Er[HID + k]);
        float gg = __ldcg(&Er[2 * HID + k]);
        float go = __ldcg(&Er[3 * HID + k]);
        if (has_gates) {
            const float* g1 = d_gates + (size_t)b * G4;
            gi += __ldcg(&g1[k]);
            gf += __ldcg(&g1[HID + k]);
            gg += __ldcg(&g1[2 * HID + k]);
            go += __ldcg(&g1[3 * HID + k]);
        }
        size_t i = (size_t)b * HID + k;
        float cc = czero ? 0.f : d_c[i];
        float c2 = sigmoidf_(gf) * cc + sigmoidf_(gi) * tanhf(gg);
        d_c[i] = c2;
        float h2 = sigmoidf_(go) * tanhf(c2);
        d_h[i] = h2;
        __half q0, q1, q2;
        split3(h2, q0, q1, q2);
        d_h0[i] = q0; d_h1[i] = q1; d_h2[i] = q2;
    }
    __syncthreads();

    // head: logits[64x64] = h @ head_w^T + head_b
    float (*shh)[65] = (float (*)[65])pchar;
    float (*shw)[65] = (float (*)[65])(pchar + 64 * 65 * 4);
    const int ty = htid >> 4, tx = htid & 15;
    float acc[4][4];
#pragma unroll
    for (int i = 0; i < 4; i++)
#pragma unroll
        for (int j = 0; j < 4; j++) acc[i][j] = 0.f;

    for (int kc = 0; kc < HID; kc += 64) {
#pragma unroll
        for (int q = 0; q < 4; q++) {
            int fi = htid + q * 256;
            int row = fi >> 4, c4 = fi & 15;
            float4 v = *(const float4*)&d_h[(size_t)(b0 + row) * HID + kc + c4 * 4];
            shh[row][c4 * 4 + 0] = v.x; shh[row][c4 * 4 + 1] = v.y;
            shh[row][c4 * 4 + 2] = v.z; shh[row][c4 * 4 + 3] = v.w;
            float4 w = *(const float4*)&hw[(size_t)row * HID + kc + c4 * 4];
            shw[row][c4 * 4 + 0] = w.x; shw[row][c4 * 4 + 1] = w.y;
            shw[row][c4 * 4 + 2] = w.z; shw[row][c4 * 4 + 3] = w.w;
        }
        __syncthreads();
#pragma unroll 4
        for (int kk = 0; kk < 64; kk++) {
            float av[4], bv[4];
#pragma unroll
            for (int i = 0; i < 4; i++) av[i] = shh[ty * 4 + i][kk];
#pragma unroll
            for (int j = 0; j < 4; j++) bv[j] = shw[tx * 4 + j][kk];
#pragma unroll
            for (int i = 0; i < 4; i++)
#pragma unroll
                for (int j = 0; j < 4; j++) acc[i][j] += av[i] * bv[j];
        }
        __syncthreads();
    }
#pragma unroll
    for (int i = 0; i < 4; i++)
#pragma unroll
        for (int j = 0; j < 4; j++)
            d_logits[(size_t)(b0 + ty * 4 + i) * ALPH + tx * 4 + j] = acc[i][j] + hb[tx * 4 + j];
}

// ---------------- the one persistent kernel ----------------
__global__ __launch_bounds__(NTHREADS, 1)
void k_all(const float* __restrict__ embed, const float* __restrict__ w_ih,
           const float* __restrict__ w_hh, const float* __restrict__ b_ih,
           const float* __restrict__ b_hh, const float* __restrict__ head_w,
           const float* __restrict__ head_b, float* __restrict__ out) {
    extern __shared__ __align__(16) char dsm[];
    __shared__ int s_tok[128];
    const int tid = threadIdx.x;
    const int half = tid >> 8;          // two 256-thread halves for cell/head/sample
    const int htid = tid & 255;
    int* stok_h = s_tok + half * 64;
    char* pchar_h = dsm + half * 33280; // per-half head smem (shh + shw)
    const unsigned gtid = blockIdx.x * NTHREADS + tid;
    const unsigned nth = gridDim.x * NTHREADS;
    const uint32_t dsm_u32 = smem_to_u32(dsm);

    // ---- phase 0: keys, logp zero, E precompute, W 3-limb split ----
    if (blockIdx.x == 0 && tid < SEQL) {
        uint2 y = threefry2x32(0u, 42u, 0u, (unsigned)tid);
        d_keys[2 * tid]     = y.x;
        d_keys[2 * tid + 1] = y.y;
    }
    for (unsigned i = gtid; i < BATCH; i += nth)
        out[(size_t)BATCH * SEQL + i] = 0.f;
    for (unsigned idx = gtid; idx < (ALPH + 1) * G4; idx += nth) {
        int t = idx / G4, j = idx % G4;
        const float* er = embed + t * HID;
        const float* wr = w_ih + (size_t)j * HID;
        float s = b_ih[j] + b_hh[j];
#pragma unroll 8
        for (int k = 0; k < HID; k++) s += __ldg(&er[k]) * __ldg(&wr[k]);
        d_E[idx] = s;
    }
    for (unsigned idx = gtid; idx < (unsigned)G4 * HID; idx += nth) {
        __half q0, q1, q2;
        split3(w_hh[idx], q0, q1, q2);
        d_W0[idx] = q0; d_W1[idx] = q1; d_W2[idx] = q2;
    }
    gsync();

    // ---- BOS step ----
    for (int cp2 = blockIdx.x; cp2 < BATCH / 128; cp2 += gridDim.x) {
        cell_head(cp2 * 2 + half, 0, 0, 1, stok_h, pchar_h, head_w, head_b, htid);
        __syncthreads();
    }
    gsync();

    // ---- main loop ----
    for (int t = 0; t < SEQL; t++) {
        if (t < SEQL - 1) {
            for (int tile = blockIdx.x; tile < MTILE * NTILE; tile += gridDim.x)
                gemm_tile_merged(tile, dsm_u32);
        }
        gsync();
        for (int cp2 = blockIdx.x; cp2 < BATCH / 128; cp2 += gridDim.x) {
            int ch = cp2 * 2 + half;
            sample_chunk(ch, t, stok_h, out, htid);
            if (t < SEQL - 1) {
                __syncthreads();
                cell_head(ch, 1, 1, 0, stok_h, pchar_h, head_w, head_b, htid);
            }
            __syncthreads();
        }
        gsync();
    }
}

// ---------------- launch ----------------
extern "C" void kernel_launch(void* const* d_in, const int* in_sizes, int n_in,
                              void* d_out, int out_size) {
    int off = (in_sizes[0] == (ALPH + 1) * HID) ? 0 : 1;
    const float* embed  = (const float*)d_in[off + 0];
    const float* w_ih   = (const float*)d_in[off + 1];
    const float* w_hh   = (const float*)d_in[off + 2];
    const float* b_ih   = (const float*)d_in[off + 3];
    const float* b_hh   = (const float*)d_in[off + 4];
    const float* head_w = (const float*)d_in[off + 5];
    const float* head_b = (const float*)d_in[off + 6];
    float* out = (float*)d_out;

    int dev = 0;
    cudaGetDevice(&dev);
    int nsm = 148;
    cudaDeviceGetAttribute(&nsm, cudaDevAttrMultiProcessorCount, dev);

    cudaFuncSetAttribute(k_all, cudaFuncAttributeMaxDynamicSharedMemorySize, DSM_BYTES);

    // grid must exactly match co-resident capacity for the gsync barrier
    int occ = 1;
    if (cudaOccupancyMaxActiveBlocksPerMultiprocessor(&occ, k_all, NTHREADS, DSM_BYTES)
        != cudaSuccess || occ < 1)
        occ = 1;
    if (occ > 2) occ = 2;

    k_all<<<nsm * occ, NTHREADS, DSM_BYTES>>>(embed, w_ih, w_hh, b_ih, b_hh,
                                              head_w, head_b, out);
}